// round 3
// baseline (speedup 1.0000x reference)
#include <cuda_runtime.h>
#include <math_constants.h>

#define NN 10000
#define NE 320000

// ---------------- scratch (static device globals; no runtime allocation) ----------------
__device__ float g_feat1[NN * 256];   // layer-1 projected features [N, H*D]
__device__ float g_h[NN * 256];       // layer-1 output after edge-softmax agg + elu
__device__ float g_el1[NN * 4];
__device__ float g_er1[NN * 4];
__device__ float g_feat2[NN * 47];
__device__ float g_el2[NN];
__device__ float g_er2[NN];
__device__ int   g_deg[NN];
__device__ int   g_cur[NN];
__device__ int   g_rowstart[NN + 1];
__device__ int   g_csr_src[NE];

__device__ __forceinline__ float lrelu(float x) { return x > 0.f ? x : 0.2f * x; }

// ---------------- CSR build ----------------
__global__ void init_kernel() {
    int i = blockIdx.x * blockDim.x + threadIdx.x;
    if (i < NN) { g_deg[i] = 0; g_cur[i] = 0; }
}

__global__ void count_kernel(const int* __restrict__ dst) {
    int e = blockIdx.x * blockDim.x + threadIdx.x;
    if (e < NE) atomicAdd(&g_deg[dst[e]], 1);
}

__global__ void scan_kernel() {
    __shared__ int sh[1024];
    int t = threadIdx.x;
    const int CH = 10;                 // 1024*10 >= NN
    int base = t * CH;
    int local[CH];
    int s = 0;
#pragma unroll
    for (int i = 0; i < CH; i++) {
        int idx = base + i;
        int d = (idx < NN) ? g_deg[idx] : 0;
        local[i] = d; s += d;
    }
    sh[t] = s;
    __syncthreads();
    for (int off = 1; off < 1024; off <<= 1) {
        int v = (t >= off) ? sh[t - off] : 0;
        __syncthreads();
        sh[t] += v;
        __syncthreads();
    }
    int offset = sh[t] - s;            // exclusive prefix
#pragma unroll
    for (int i = 0; i < CH; i++) {
        int idx = base + i;
        if (idx < NN) g_rowstart[idx] = offset;
        offset += local[i];
    }
    if (t == 1023) g_rowstart[NN] = offset;   // == NE
}

__global__ void scatter_kernel(const int* __restrict__ src, const int* __restrict__ dst) {
    int e = blockIdx.x * blockDim.x + threadIdx.x;
    if (e < NE) {
        int d = dst[e];
        int pos = g_rowstart[d] + atomicAdd(&g_cur[d], 1);
        g_csr_src[pos] = src[e];
    }
}

// ---------------- GEMM1: feat1 = features @ W1   ([NN,256] x [256,256]) ----------------
__global__ void gemm1_kernel(const float* __restrict__ A, const float* __restrict__ B) {
    __shared__ float As[16][64];
    __shared__ float Bs[16][64];
    int tid = threadIdx.x;             // 256 threads
    int tx = tid & 15, ty = tid >> 4;
    int rowBase = blockIdx.y * 64, colBase = blockIdx.x * 64;
    float acc[4][4] = {};

    int la = tid * 4;
    int arw = la >> 4;                 // A-tile row (0..63)
    int ac  = la & 15;                 // A-tile k   (0,4,8,12)
    int br  = la >> 6;                 // B-tile k   (0..15)
    int bc  = la & 63;                 // B-tile col (multiple of 4)

    for (int k0 = 0; k0 < 256; k0 += 16) {
        int row = rowBase + arw;
        float4 va = (row < NN) ? *(const float4*)&A[row * 256 + k0 + ac]
                               : make_float4(0.f, 0.f, 0.f, 0.f);
        As[ac + 0][arw] = va.x; As[ac + 1][arw] = va.y;
        As[ac + 2][arw] = va.z; As[ac + 3][arw] = va.w;
        float4 vb = *(const float4*)&B[(k0 + br) * 256 + colBase + bc];
        *(float4*)&Bs[br][bc] = vb;
        __syncthreads();
#pragma unroll
        for (int k = 0; k < 16; k++) {
            float a[4], b[4];
#pragma unroll
            for (int i = 0; i < 4; i++) a[i] = As[k][ty * 4 + i];
#pragma unroll
            for (int j = 0; j < 4; j++) b[j] = Bs[k][tx * 4 + j];
#pragma unroll
            for (int i = 0; i < 4; i++)
#pragma unroll
                for (int j = 0; j < 4; j++) acc[i][j] = fmaf(a[i], b[j], acc[i][j]);
        }
        __syncthreads();
    }
#pragma unroll
    for (int i = 0; i < 4; i++) {
        int row = rowBase + ty * 4 + i;
        if (row < NN)
            *(float4*)&g_feat1[row * 256 + colBase + tx * 4] =
                make_float4(acc[i][0], acc[i][1], acc[i][2], acc[i][3]);
    }
}

// ---------------- el1/er1: per-(node,head) dot of feat1 with attn vectors ----------------
__global__ void elr1_kernel(const float* __restrict__ al1, const float* __restrict__ ar1) {
    int gw = (blockIdx.x * blockDim.x + threadIdx.x) >> 5;
    int lane = threadIdx.x & 31;
    if (gw >= NN * 4) return;
    int node = gw >> 2, h = gw & 3;
    const float* f = g_feat1 + node * 256 + h * 64;
    float f0 = f[lane], f1 = f[lane + 32];
    float a0 = al1[h * 64 + lane], a1 = al1[h * 64 + lane + 32];
    float b0 = ar1[h * 64 + lane], b1 = ar1[h * 64 + lane + 32];
    float se = fmaf(f0, a0, f1 * a1);
    float sr = fmaf(f0, b0, f1 * b1);
#pragma unroll
    for (int off = 16; off; off >>= 1) {
        se += __shfl_xor_sync(0xffffffffu, se, off);
        sr += __shfl_xor_sync(0xffffffffu, sr, off);
    }
    if (lane == 0) { g_el1[gw] = se; g_er1[gw] = sr; }
}

// ---------------- layer-1 edge softmax + aggregation + ELU (warp per dst node) ----------------
__global__ void gather1_kernel() {
    int gw = (blockIdx.x * blockDim.x + threadIdx.x) >> 5;
    int lane = threadIdx.x & 31;
    if (gw >= NN) return;
    int node = gw;
    int beg = g_rowstart[node], end = g_rowstart[node + 1];
    float4 er4 = *(const float4*)&g_er1[node * 4];

    // pass A: per-head max (lanes stride edges)
    float mx0 = -CUDART_INF_F, mx1 = -CUDART_INF_F, mx2 = -CUDART_INF_F, mx3 = -CUDART_INF_F;
    for (int i = beg + lane; i < end; i += 32) {
        int s = g_csr_src[i];
        float4 e4 = *(const float4*)&g_el1[s * 4];
        mx0 = fmaxf(mx0, lrelu(e4.x + er4.x));
        mx1 = fmaxf(mx1, lrelu(e4.y + er4.y));
        mx2 = fmaxf(mx2, lrelu(e4.z + er4.z));
        mx3 = fmaxf(mx3, lrelu(e4.w + er4.w));
    }
#pragma unroll
    for (int off = 16; off; off >>= 1) {
        mx0 = fmaxf(mx0, __shfl_xor_sync(0xffffffffu, mx0, off));
        mx1 = fmaxf(mx1, __shfl_xor_sync(0xffffffffu, mx1, off));
        mx2 = fmaxf(mx2, __shfl_xor_sync(0xffffffffu, mx2, off));
        mx3 = fmaxf(mx3, __shfl_xor_sync(0xffffffffu, mx3, off));
    }
    if (!(mx0 > -CUDART_INF_F)) mx0 = 0.f;   // empty-segment guard (matches reference)
    if (!(mx1 > -CUDART_INF_F)) mx1 = 0.f;
    if (!(mx2 > -CUDART_INF_F)) mx2 = 0.f;
    if (!(mx3 > -CUDART_INF_F)) mx3 = 0.f;

    // pass B: per-head exp-sum
    float dn0 = 0.f, dn1 = 0.f, dn2 = 0.f, dn3 = 0.f;
    for (int i = beg + lane; i < end; i += 32) {
        int s = g_csr_src[i];
        float4 e4 = *(const float4*)&g_el1[s * 4];
        dn0 += __expf(lrelu(e4.x + er4.x) - mx0);
        dn1 += __expf(lrelu(e4.y + er4.y) - mx1);
        dn2 += __expf(lrelu(e4.z + er4.z) - mx2);
        dn3 += __expf(lrelu(e4.w + er4.w) - mx3);
    }
#pragma unroll
    for (int off = 16; off; off >>= 1) {
        dn0 += __shfl_xor_sync(0xffffffffu, dn0, off);
        dn1 += __shfl_xor_sync(0xffffffffu, dn1, off);
        dn2 += __shfl_xor_sync(0xffffffffu, dn2, off);
        dn3 += __shfl_xor_sync(0xffffffffu, dn3, off);
    }
    float inv0 = 1.f / fmaxf(dn0, 1e-9f);
    float inv1 = 1.f / fmaxf(dn1, 1e-9f);
    float inv2 = 1.f / fmaxf(dn2, 1e-9f);
    float inv3 = 1.f / fmaxf(dn3, 1e-9f);

    // pass C: weighted feature accumulation. Lane owns 8 contiguous cols -> one head.
    int h = lane >> 3;
    float mxh  = (h == 0) ? mx0 : (h == 1) ? mx1 : (h == 2) ? mx2 : mx3;
    float invh = (h == 0) ? inv0 : (h == 1) ? inv1 : (h == 2) ? inv2 : inv3;
    float erh  = (h == 0) ? er4.x : (h == 1) ? er4.y : (h == 2) ? er4.z : er4.w;

    float4 acc0 = make_float4(0.f, 0.f, 0.f, 0.f);
    float4 acc1 = make_float4(0.f, 0.f, 0.f, 0.f);
    for (int i = beg; i < end; i++) {
        int s = g_csr_src[i];                       // warp-uniform broadcast load
        float v = lrelu(g_el1[s * 4 + h] + erh);
        float a = __expf(v - mxh) * invh;
        const float4* fr = (const float4*)&g_feat1[s * 256 + lane * 8];
        float4 f0 = fr[0], f1 = fr[1];
        acc0.x = fmaf(a, f0.x, acc0.x); acc0.y = fmaf(a, f0.y, acc0.y);
        acc0.z = fmaf(a, f0.z, acc0.z); acc0.w = fmaf(a, f0.w, acc0.w);
        acc1.x = fmaf(a, f1.x, acc1.x); acc1.y = fmaf(a, f1.y, acc1.y);
        acc1.z = fmaf(a, f1.z, acc1.z); acc1.w = fmaf(a, f1.w, acc1.w);
    }
    // ELU
    acc0.x = acc0.x > 0.f ? acc0.x : __expf(acc0.x) - 1.f;
    acc0.y = acc0.y > 0.f ? acc0.y : __expf(acc0.y) - 1.f;
    acc0.z = acc0.z > 0.f ? acc0.z : __expf(acc0.z) - 1.f;
    acc0.w = acc0.w > 0.f ? acc0.w : __expf(acc0.w) - 1.f;
    acc1.x = acc1.x > 0.f ? acc1.x : __expf(acc1.x) - 1.f;
    acc1.y = acc1.y > 0.f ? acc1.y : __expf(acc1.y) - 1.f;
    acc1.z = acc1.z > 0.f ? acc1.z : __expf(acc1.z) - 1.f;
    acc1.w = acc1.w > 0.f ? acc1.w : __expf(acc1.w) - 1.f;
    *(float4*)&g_h[node * 256 + lane * 8]     = acc0;
    *(float4*)&g_h[node * 256 + lane * 8 + 4] = acc1;
}

// ---------------- GEMM2 fused with el2/er2: feat2 = h @ W2, attn dots ----------------
__global__ void gemm2_kernel(const float* __restrict__ W2,
                             const float* __restrict__ al2,
                             const float* __restrict__ ar2) {
    __shared__ float Ws[256 * 48];     // padded to 48 cols, col 47 = 0
    int tid = threadIdx.x;             // 256 threads
    for (int idx = tid; idx < 256 * 48; idx += 256) {
        int k = idx / 48, j = idx - k * 48;
        Ws[idx] = (j < 47) ? W2[k * 47 + j] : 0.f;
    }
    __syncthreads();

    int lane = tid & 31, warp = tid >> 5;
    int j1 = lane + 32;
    int j1c = j1 < 47 ? j1 : 47;       // clamped index hits zero-padded col
    float av0 = al2[lane];
    float av1 = (j1 < 47) ? al2[j1] : 0.f;
    float bv0 = ar2[lane];
    float bv1 = (j1 < 47) ? ar2[j1] : 0.f;

    int warpsTotal = gridDim.x * 8;
    for (int row = blockIdx.x * 8 + warp; row < NN; row += warpsTotal) {
        float acc0 = 0.f, acc1 = 0.f;
        const float* hr = g_h + row * 256;
        for (int kk = 0; kk < 256; kk += 32) {
            float hv = hr[kk + lane];
#pragma unroll
            for (int t2 = 0; t2 < 32; t2++) {
                float v = __shfl_sync(0xffffffffu, hv, t2);
                int kb = (kk + t2) * 48;
                acc0 = fmaf(v, Ws[kb + lane], acc0);
                acc1 = fmaf(v, Ws[kb + j1c], acc1);
            }
        }
        if (lane < 47) g_feat2[row * 47 + lane] = acc0;
        if (j1 < 47)   g_feat2[row * 47 + j1]  = acc1;
        float pe = fmaf(acc0, av0, acc1 * av1);
        float pr = fmaf(acc0, bv0, acc1 * bv1);
#pragma unroll
        for (int off = 16; off; off >>= 1) {
            pe += __shfl_xor_sync(0xffffffffu, pe, off);
            pr += __shfl_xor_sync(0xffffffffu, pr, off);
        }
        if (lane == 0) { g_el2[row] = pe; g_er2[row] = pr; }
    }
}

// ---------------- layer-2 gather + fused log-softmax (warp per dst node) ----------------
__global__ void gather2_kernel(float* __restrict__ out) {
    int gw = (blockIdx.x * blockDim.x + threadIdx.x) >> 5;
    int lane = threadIdx.x & 31;
    if (gw >= NN) return;
    int node = gw;
    int beg = g_rowstart[node], end = g_rowstart[node + 1];
    float erv = g_er2[node];

    float mx = -CUDART_INF_F;
    for (int i = beg + lane; i < end; i += 32)
        mx = fmaxf(mx, lrelu(g_el2[g_csr_src[i]] + erv));
#pragma unroll
    for (int off = 16; off; off >>= 1)
        mx = fmaxf(mx, __shfl_xor_sync(0xffffffffu, mx, off));
    if (!(mx > -CUDART_INF_F)) mx = 0.f;

    float dn = 0.f;
    for (int i = beg + lane; i < end; i += 32)
        dn += __expf(lrelu(g_el2[g_csr_src[i]] + erv) - mx);
#pragma unroll
    for (int off = 16; off; off >>= 1)
        dn += __shfl_xor_sync(0xffffffffu, dn, off);
    float inv = 1.f / fmaxf(dn, 1e-9f);

    int j1 = lane + 32;
    float acc0 = 0.f, acc1 = 0.f;
    for (int i = beg; i < end; i++) {
        int s = g_csr_src[i];
        float a = __expf(lrelu(g_el2[s] + erv) - mx) * inv;
        acc0 = fmaf(a, g_feat2[s * 47 + lane], acc0);
        if (j1 < 47) acc1 = fmaf(a, g_feat2[s * 47 + j1], acc1);
    }

    // log_softmax over 47 logits
    float m2 = fmaxf(acc0, (j1 < 47) ? acc1 : -CUDART_INF_F);
#pragma unroll
    for (int off = 16; off; off >>= 1)
        m2 = fmaxf(m2, __shfl_xor_sync(0xffffffffu, m2, off));
    float se = __expf(acc0 - m2) + ((j1 < 47) ? __expf(acc1 - m2) : 0.f);
#pragma unroll
    for (int off = 16; off; off >>= 1)
        se += __shfl_xor_sync(0xffffffffu, se, off);
    float ls = logf(se);
    out[node * 47 + lane] = acc0 - m2 - ls;
    if (j1 < 47) out[node * 47 + j1] = acc1 - m2 - ls;
}

// ---------------- launch ----------------
extern "C" void kernel_launch(void* const* d_in, const int* in_sizes, int n_in,
                              void* d_out, int out_size) {
    const float* features = (const float*)d_in[0];
    const int*   src      = (const int*)  d_in[1];
    const int*   dst      = (const int*)  d_in[2];
    const float* W1       = (const float*)d_in[3];
    const float* al1      = (const float*)d_in[4];
    const float* ar1      = (const float*)d_in[5];
    const float* W2       = (const float*)d_in[6];
    const float* al2      = (const float*)d_in[7];
    const float* ar2      = (const float*)d_in[8];
    float* out = (float*)d_out;

    init_kernel<<<(NN + 255) / 256, 256>>>();
    count_kernel<<<(NE + 255) / 256, 256>>>(dst);
    scan_kernel<<<1, 1024>>>();
    scatter_kernel<<<(NE + 255) / 256, 256>>>(src, dst);

    dim3 g1(4, (NN + 63) / 64);
    gemm1_kernel<<<g1, 256>>>(features, W1);
    elr1_kernel<<<(NN * 4 + 7) / 8, 256>>>(al1, ar1);
    gather1_kernel<<<(NN + 7) / 8, 256>>>();
    gemm2_kernel<<<160, 256>>>(W2, al2, ar2);
    gather2_kernel<<<(NN + 7) / 8, 256>>>(out);
}